// round 8
// baseline (speedup 1.0000x reference)
#include <cuda_runtime.h>

namespace {
constexpr int PNP = 4;
constexpr int MOD = 4;
constexpr int NCH = 100;
constexpr int F   = NCH + PNP;       // 104
constexpr int FM  = F * MOD;         // 416
constexpr int XW  = PNP * (1 + MOD); // 20
constexpr int NT  = 224;             // 7 warps, 2 lanes/row
constexpr int HALF = 52;
constexpr int QSTR = F;
constexpr int QSZ  = MOD * QSTR;     // 416
constexpr float C0F   = 299792458.0f;
constexpr float ALPHA = 2.3025850929940457e-4f;
}

using ull = unsigned long long;

__device__ __forceinline__ ull pk2(float a, float b) {
    ull r; asm("mov.b64 %0,{%1,%2};" : "=l"(r) : "f"(a), "f"(b)); return r;
}
__device__ __forceinline__ void fma2(ull& d, ull a, ull b) {
    asm("fma.rn.f32x2 %0,%1,%2,%0;" : "+l"(d) : "l"(a), "l"(b));
}
__device__ __forceinline__ float up2sum(ull v) {
    float lo, hi; asm("mov.b64 {%0,%1},%2;" : "=f"(lo), "=f"(hi) : "l"(v));
    return lo + hi;
}

__global__ __launch_bounds__(NT, 4) void raman_kernel(
    const float* __restrict__ x,
    const float* __restrict__ sig_freq,
    const float* __restrict__ sig_pow,
    const float* __restrict__ sig_loss,
    const float* __restrict__ lcoef,
    const float* __restrict__ overlap,
    const float* __restrict__ raman,
    const int*   __restrict__ steps_p,
    const float* __restrict__ length_p,
    const float* __restrict__ maxf_p,
    int Lr,
    float* __restrict__ out)
{
    __shared__ float Qt[2 * QSZ];
    __shared__ float frq[F];
    __shared__ float lossS[FM];
    __shared__ float PcS[FM];
    __shared__ float accS[FM];
    __shared__ float ovS[16];

    const int b = blockIdx.x;
    const int t = threadIdx.x;
    const int w = t >> 5;
    const int l = t & 31;
    const int row  = w * 16 + (l >> 1);
    const int half = l & 1;
    const int rowc = min(row, F - 1);
    const bool active = (row < F);
    const float* xb = x + b * XW;

    const int   steps  = *steps_p;
    const float length = *length_p;
    const float maxf   = *maxf_p;
    const float h  = length / (float)(steps - 1);
    const float h2 = 0.5f * h;
    const float h6 = h * (1.0f / 6.0f);

    if (t < 16) ovS[t] = overlap[t];
    for (int u = t; u < F; u += NT)
        frq[u] = (u < PNP) ? (C0F / xb[u]) : sig_freq[u - PNP];
    {
        const float lc0 = lcoef[0], lc1 = lcoef[1], lc2 = lcoef[2];
        for (int u = t; u < FM; u += NT) {
            float lv, pv;
            if (u < PNP * MOD) {
                const float wn = xb[u >> 2] * 1e9f;
                lv = (lc2 + lc1 * wn + lc0 * wn * wn) * ALPHA;
                pv = xb[PNP + u];
            } else {
                lv = sig_loss[u - PNP * MOD];
                pv = sig_pow[u - PNP * MOD];
            }
            lossS[u] = lv; PcS[u] = pv;
        }
    }
    __syncthreads();

    // ---- this lane's 52 gains, computed directly into packed reg pairs ----
    ull gp[HALF / 2];
    {
        const float scale = (float)(Lr - 1) / maxf;
        const float fi = frq[rowc];
        #pragma unroll 4
        for (int k = 0; k < HALF / 2; ++k) {
            float gv[2];
            #pragma unroll
            for (int e = 0; e < 2; ++e) {
                const int j = half * HALF + 2 * k + e;
                const float fj = frq[j];
                const float fd = fj - fi;
                const float pos = fabsf(fd) * scale;
                int i0 = (int)floorf(pos);
                i0 = min(max(i0, 0), Lr - 2);
                const float wgt = pos - (float)i0;
                float g = raman[i0] * (1.0f - wgt) + raman[i0 + 1] * wgt;
                if (fd < 0.0f) g = -g;
                gv[e] = g * fmaxf(1.0f, fi / fj);
            }
            gp[k] = pk2(gv[0], gv[1]);
        }
    }

    // ---- initial power into regs + prologue Q(P0) ----
    float pk0, pk1, pkv2, pk3;
    {
        const float4 p0 = *(const float4*)(PcS + 4 * rowc);
        pk0 = p0.x; pk1 = p0.y; pkv2 = p0.z; pk3 = p0.w;
        const ulonglong2 ovp = ((const ulonglong2*)ovS)[half * 2 + 0];
        const ulonglong2 ovq = ((const ulonglong2*)ovS)[half * 2 + 1];
        const ull p01 = pk2(pk0, pk1), p23 = pk2(pkv2, pk3);
        ull t0 = 0, t1 = 0;
        fma2(t0, ovp.x, p01); fma2(t0, ovp.y, p23);
        fma2(t1, ovq.x, p01); fma2(t1, ovq.y, p23);
        if (active) {
            Qt[(2 * half + 0) * QSTR + row] = up2sum(t0);
            Qt[(2 * half + 1) * QSTR + row] = up2sum(t1);
        }
    }
    __syncthreads();

    const int nst = 4 * (steps - 1);
    int cur = 0;

    for (int it = 0; it < nst; ++it) {
        const int s4 = it & 3;
        // ---- matvec over this lane's 52 j's ----
        ull a0 = 0, a1 = 0, a2 = 0, a3 = 0;
        const float* Qc = Qt + cur * QSZ + half * HALF;
        #pragma unroll
        for (int j4 = 0; j4 < HALF; j4 += 4) {
            const int k = j4 >> 1;
            const ulonglong2 q0 = *(const ulonglong2*)(Qc + 0 * QSTR + j4);
            const ulonglong2 q1 = *(const ulonglong2*)(Qc + 1 * QSTR + j4);
            const ulonglong2 q2 = *(const ulonglong2*)(Qc + 2 * QSTR + j4);
            const ulonglong2 q3 = *(const ulonglong2*)(Qc + 3 * QSTR + j4);
            fma2(a0, gp[k], q0.x); fma2(a0, gp[k + 1], q0.y);
            fma2(a1, gp[k], q1.x); fma2(a1, gp[k + 1], q1.y);
            fma2(a2, gp[k], q2.x); fma2(a2, gp[k + 1], q2.y);
            fma2(a3, gp[k], q3.x); fma2(a3, gp[k + 1], q3.y);
        }
        float A0 = up2sum(a0), A1 = up2sum(a1);
        float A2 = up2sum(a2), A3 = up2sum(a3);
        A0 += __shfl_xor_sync(0xffffffffu, A0, 1);
        A1 += __shfl_xor_sync(0xffffffffu, A1, 1);
        A2 += __shfl_xor_sync(0xffffffffu, A2, 1);
        A3 += __shfl_xor_sync(0xffffffffu, A3, 1);

        const float4 lv = *(const float4*)(lossS + 4 * rowc);
        const float k0 = (A0 - lv.x) * pk0;
        const float k1 = (A1 - lv.y) * pk1;
        const float k2 = (A2 - lv.z) * pkv2;
        const float k3 = (A3 - lv.w) * pk3;

        float4 av;
        if (s4 == 0) {
            av = make_float4(k0, k1, k2, k3);
        } else {
            av = *(const float4*)(accS + 4 * rowc);
            const float c = (s4 == 3) ? 1.0f : 2.0f;
            av.x = fmaf(c, k0, av.x); av.y = fmaf(c, k1, av.y);
            av.z = fmaf(c, k2, av.z); av.w = fmaf(c, k3, av.w);
        }
        const float4 pc = *(const float4*)(PcS + 4 * rowc);
        if (s4 < 3) {
            if (active && half == 0) *(float4*)(accS + 4 * row) = av;
            const float cs = (s4 == 2) ? h : h2;
            pk0 = fmaf(cs, k0, pc.x); pk1 = fmaf(cs, k1, pc.y);
            pkv2 = fmaf(cs, k2, pc.z); pk3 = fmaf(cs, k3, pc.w);
        } else {
            pk0 = fmaf(h6, av.x, pc.x); pk1 = fmaf(h6, av.y, pc.y);
            pkv2 = fmaf(h6, av.z, pc.z); pk3 = fmaf(h6, av.w, pc.w);
            if (active && half == 0)
                *(float4*)(PcS + 4 * row) = make_float4(pk0, pk1, pkv2, pk3);
        }

        // ---- Q for next stage (this lane's two modes) ----
        {
            const ulonglong2 ovp = ((const ulonglong2*)ovS)[half * 2 + 0];
            const ulonglong2 ovq = ((const ulonglong2*)ovS)[half * 2 + 1];
            const ull p01 = pk2(pk0, pk1), p23 = pk2(pkv2, pk3);
            ull t0 = 0, t1 = 0;
            fma2(t0, ovp.x, p01); fma2(t0, ovp.y, p23);
            fma2(t1, ovq.x, p01); fma2(t1, ovq.y, p23);
            float* Qn = Qt + (cur ^ 1) * QSZ;
            if (active) {
                Qn[(2 * half + 0) * QSTR + row] = up2sum(t0);
                Qn[(2 * half + 1) * QSTR + row] = up2sum(t1);
            }
        }
        __syncthreads();
        cur ^= 1;
    }

    if (active && row >= PNP && half == 0)
        *(float4*)(out + b * (NCH * MOD) + (row - PNP) * 4) =
            make_float4(pk0, pk1, pkv2, pk3);
}

extern "C" void kernel_launch(void* const* d_in, const int* in_sizes, int n_in,
                              void* d_out, int out_size) {
    const float* x        = (const float*)d_in[0];
    const float* sig_freq = (const float*)d_in[1];
    const float* sig_pow  = (const float*)d_in[2];
    const float* sig_loss = (const float*)d_in[3];
    const float* lcoef    = (const float*)d_in[4];
    const float* overlap  = (const float*)d_in[5];
    const float* raman    = (const float*)d_in[6];
    const int*   steps_p  = (const int*)d_in[10];
    const float* length_p = (const float*)d_in[11];
    const float* maxf_p   = (const float*)d_in[12];

    const int B  = in_sizes[0] / XW;
    const int Lr = in_sizes[6];

    raman_kernel<<<B, NT>>>(x, sig_freq, sig_pow, sig_loss, lcoef, overlap,
                            raman, steps_p, length_p, maxf_p, Lr,
                            (float*)d_out);
}

// round 9
// speedup vs baseline: 1.0585x; 1.0585x over previous
#include <cuda_runtime.h>

namespace {
constexpr int PNP = 4;
constexpr int MOD = 4;
constexpr int NCH = 100;
constexpr int F   = NCH + PNP;       // 104
constexpr int XW  = PNP * (1 + MOD); // 20
constexpr int NT  = 224;             // 7 warps, 2 lanes/row
constexpr int HALF = 52;
constexpr int QSTR = F;
constexpr int QSZ  = MOD * QSTR;     // 416
constexpr float C0F   = 299792458.0f;
constexpr float ALPHA = 2.3025850929940457e-4f;
}

using ull = unsigned long long;

__device__ __forceinline__ ull pk2(float a, float b) {
    ull r; asm("mov.b64 %0,{%1,%2};" : "=l"(r) : "f"(a), "f"(b)); return r;
}
__device__ __forceinline__ void fma2(ull& d, ull a, ull b) {
    asm("fma.rn.f32x2 %0,%1,%2,%0;" : "+l"(d) : "l"(a), "l"(b));
}
__device__ __forceinline__ float up2sum(ull v) {
    float lo, hi; asm("mov.b64 {%0,%1},%2;" : "=f"(lo), "=f"(hi) : "l"(v));
    return lo + hi;
}

__global__ __launch_bounds__(NT, 4) void raman_kernel(
    const float* __restrict__ x,
    const float* __restrict__ sig_freq,
    const float* __restrict__ sig_pow,
    const float* __restrict__ sig_loss,
    const float* __restrict__ lcoef,
    const float* __restrict__ overlap,
    const float* __restrict__ raman,
    const int*   __restrict__ steps_p,
    const float* __restrict__ length_p,
    const float* __restrict__ maxf_p,
    int Lr,
    float* __restrict__ out)
{
    __shared__ __align__(16) float Qt[2 * QSZ];
    __shared__ __align__(16) float ovS[16];
    __shared__ float frq[F];

    const int b = blockIdx.x;
    const int t = threadIdx.x;
    const int w = t >> 5;
    const int l = t & 31;
    const int row  = w * 16 + (l >> 1);
    const int half = l & 1;
    const int m0   = 2 * half;          // this lane's first owned mode
    const int rowc = min(row, F - 1);
    const bool active = (row < F);
    const float* xb = x + b * XW;

    const int   steps  = *steps_p;
    const float length = *length_p;
    const float maxf   = *maxf_p;
    const float h  = length / (float)(steps - 1);
    const float h2 = 0.5f * h;
    const float h6 = h * (1.0f / 6.0f);

    if (t < 16) ovS[t] = overlap[t];
    for (int u = t; u < F; u += NT)
        frq[u] = (u < PNP) ? (C0F / xb[u]) : sig_freq[u - PNP];
    __syncthreads();

    // ---- this lane's 52 gains -> packed reg pairs ----
    ull gp[HALF / 2];
    {
        const float scale = (float)(Lr - 1) / maxf;
        const float fi = frq[rowc];
        #pragma unroll 4
        for (int k = 0; k < HALF / 2; ++k) {
            float gv[2];
            #pragma unroll
            for (int e = 0; e < 2; ++e) {
                const int j = half * HALF + 2 * k + e;
                const float fj = frq[j];
                const float fd = fj - fi;
                const float pos = fabsf(fd) * scale;
                int i0 = (int)floorf(pos);
                i0 = min(max(i0, 0), Lr - 2);
                const float wgt = pos - (float)i0;
                float g = raman[i0] * (1.0f - wgt) + raman[i0 + 1] * wgt;
                if (fd < 0.0f) g = -g;
                gv[e] = g * fmaxf(1.0f, fi / fj);
            }
            gp[k] = pk2(gv[0], gv[1]);
        }
    }

    // ---- per-lane RK state: ONLY this lane's two modes ----
    float lsA, lsB, pkA, pkB;
    if (rowc < PNP) {
        const float wn = xb[rowc] * 1e9f;
        const float lv = (lcoef[2] + lcoef[1] * wn + lcoef[0] * wn * wn) * ALPHA;
        lsA = lsB = lv;
        pkA = xb[PNP + 4 * rowc + m0];
        pkB = xb[PNP + 4 * rowc + m0 + 1];
    } else {
        const int u = 4 * rowc - PNP * MOD;
        lsA = sig_loss[u + m0]; lsB = sig_loss[u + m0 + 1];
        pkA = sig_pow[u + m0];  pkB = sig_pow[u + m0 + 1];
    }
    float pcA = pkA, pcB = pkB, acA = 0.f, acB = 0.f;

    // ---- prologue: Q(P0) into buffer 0 ----
    {
        const float u0 = __shfl_xor_sync(0xffffffffu, pkA, 1);
        const float u1 = __shfl_xor_sync(0xffffffffu, pkB, 1);
        const ull p01 = half ? pk2(u0, u1) : pk2(pkA, pkB);
        const ull p23 = half ? pk2(pkA, pkB) : pk2(u0, u1);
        const ulonglong2 ova = ((const ulonglong2*)ovS)[m0];
        const ulonglong2 ovb = ((const ulonglong2*)ovS)[m0 + 1];
        ull t0 = 0, t1 = 0;
        fma2(t0, ova.x, p01); fma2(t0, ova.y, p23);
        fma2(t1, ovb.x, p01); fma2(t1, ovb.y, p23);
        if (active) {
            Qt[(m0 + 0) * QSTR + row] = up2sum(t0);
            Qt[(m0 + 1) * QSTR + row] = up2sum(t1);
        }
    }
    __syncthreads();

    const int nst = 4 * (steps - 1);
    int cur = 0;
    float fo0 = 0.f, fo1 = 0.f, fo2 = 0.f, fo3 = 0.f;  // full P quad (for output)

    for (int it = 0; it < nst; ++it) {
        const int s4 = it & 3;
        // ---- matvec partials over this lane's 52 j's, all 4 modes ----
        ull a0 = 0, a1 = 0, a2 = 0, a3 = 0;
        const float* Qc = Qt + cur * QSZ + half * HALF;
        #pragma unroll
        for (int j4 = 0; j4 < HALF; j4 += 4) {
            const int k = j4 >> 1;
            const ulonglong2 q0 = *(const ulonglong2*)(Qc + 0 * QSTR + j4);
            const ulonglong2 q1 = *(const ulonglong2*)(Qc + 1 * QSTR + j4);
            const ulonglong2 q2 = *(const ulonglong2*)(Qc + 2 * QSTR + j4);
            const ulonglong2 q3 = *(const ulonglong2*)(Qc + 3 * QSTR + j4);
            fma2(a0, gp[k], q0.x); fma2(a0, gp[k + 1], q0.y);
            fma2(a1, gp[k], q1.x); fma2(a1, gp[k + 1], q1.y);
            fma2(a2, gp[k], q2.x); fma2(a2, gp[k + 1], q2.y);
            fma2(a3, gp[k], q3.x); fma2(a3, gp[k + 1], q3.y);
        }
        const float pA0 = up2sum(a0), pA1 = up2sum(a1);
        const float pA2 = up2sum(a2), pA3 = up2sum(a3);

        // exchange: lane needs partner's partials for ITS two modes only.
        // send what the partner needs (its modes), receive what I need.
        const float rA = __shfl_xor_sync(0xffffffffu, half ? pA0 : pA2, 1);
        const float rB = __shfl_xor_sync(0xffffffffu, half ? pA1 : pA3, 1);
        const float AmA = (half ? pA2 : pA0) + rA;
        const float AmB = (half ? pA3 : pA1) + rB;

        const float kA = (AmA - lsA) * pkA;
        const float kB = (AmB - lsB) * pkB;

        if (s4 == 0)      { acA = kA; acB = kB; }
        else if (s4 < 3)  { acA = fmaf(2.f, kA, acA); acB = fmaf(2.f, kB, acB); }
        else              { acA += kA; acB += kB; }

        if (s4 < 3) {
            const float cs = (s4 == 2) ? h : h2;
            pkA = fmaf(cs, kA, pcA);
            pkB = fmaf(cs, kB, pcB);
        } else {
            pkA = fmaf(h6, acA, pcA);
            pkB = fmaf(h6, acB, pcB);
            pcA = pkA; pcB = pkB;
        }

        // ---- rebuild full P quad, write this lane's 2 Q modes ----
        {
            const float u0 = __shfl_xor_sync(0xffffffffu, pkA, 1);
            const float u1 = __shfl_xor_sync(0xffffffffu, pkB, 1);
            fo0 = half ? u0 : pkA; fo1 = half ? u1 : pkB;
            fo2 = half ? pkA : u0; fo3 = half ? pkB : u1;
            const ull p01 = pk2(fo0, fo1), p23 = pk2(fo2, fo3);
            const ulonglong2 ova = ((const ulonglong2*)ovS)[m0];
            const ulonglong2 ovb = ((const ulonglong2*)ovS)[m0 + 1];
            ull t0 = 0, t1 = 0;
            fma2(t0, ova.x, p01); fma2(t0, ova.y, p23);
            fma2(t1, ovb.x, p01); fma2(t1, ovb.y, p23);
            float* Qn = Qt + (cur ^ 1) * QSZ;
            if (active) {
                Qn[(m0 + 0) * QSTR + row] = up2sum(t0);
                Qn[(m0 + 1) * QSTR + row] = up2sum(t1);
            }
        }
        __syncthreads();
        cur ^= 1;
    }

    if (active && row >= PNP && half == 0)
        *(float4*)(out + b * (NCH * MOD) + (row - PNP) * 4) =
            make_float4(fo0, fo1, fo2, fo3);
}

extern "C" void kernel_launch(void* const* d_in, const int* in_sizes, int n_in,
                              void* d_out, int out_size) {
    const float* x        = (const float*)d_in[0];
    const float* sig_freq = (const float*)d_in[1];
    const float* sig_pow  = (const float*)d_in[2];
    const float* sig_loss = (const float*)d_in[3];
    const float* lcoef    = (const float*)d_in[4];
    const float* overlap  = (const float*)d_in[5];
    const float* raman    = (const float*)d_in[6];
    const int*   steps_p  = (const int*)d_in[10];
    const float* length_p = (const float*)d_in[11];
    const float* maxf_p   = (const float*)d_in[12];

    const int B  = in_sizes[0] / XW;
    const int Lr = in_sizes[6];

    raman_kernel<<<B, NT>>>(x, sig_freq, sig_pow, sig_loss, lcoef, overlap,
                            raman, steps_p, length_p, maxf_p, Lr,
                            (float*)d_out);
}

// round 10
// speedup vs baseline: 1.0610x; 1.0024x over previous
#include <cuda_runtime.h>

namespace {
constexpr int PNP = 4;
constexpr int MOD = 4;
constexpr int NCH = 100;
constexpr int F   = NCH + PNP;       // 104
constexpr int XW  = PNP * (1 + MOD); // 20
constexpr int NT  = 224;             // 7 warps, 2 lanes/row
constexpr int HALF = 52;
constexpr int QSTR = F;
constexpr int QSZ  = MOD * QSTR;     // 416
constexpr float C0F   = 299792458.0f;
constexpr float ALPHA = 2.3025850929940457e-4f;
}

using ull = unsigned long long;

__device__ __forceinline__ ull pk2(float a, float b) {
    ull r; asm("mov.b64 %0,{%1,%2};" : "=l"(r) : "f"(a), "f"(b)); return r;
}
__device__ __forceinline__ void fma2(ull& d, ull a, ull b) {
    asm("fma.rn.f32x2 %0,%1,%2,%0;" : "+l"(d) : "l"(a), "l"(b));
}
__device__ __forceinline__ float up2sum(ull v) {
    float lo, hi; asm("mov.b64 {%0,%1},%2;" : "=f"(lo), "=f"(hi) : "l"(v));
    return lo + hi;
}

__global__ __launch_bounds__(NT, 4) void raman_kernel(
    const float* __restrict__ x,
    const float* __restrict__ sig_freq,
    const float* __restrict__ sig_pow,
    const float* __restrict__ sig_loss,
    const float* __restrict__ lcoef,
    const float* __restrict__ overlap,
    const float* __restrict__ raman,
    const int*   __restrict__ steps_p,
    const float* __restrict__ length_p,
    const float* __restrict__ maxf_p,
    int Lr,
    float* __restrict__ out)
{
    __shared__ __align__(16) float Qt[2 * QSZ];
    __shared__ __align__(16) float ovS[16];
    __shared__ float frq[F];

    const int b = blockIdx.x;
    const int t = threadIdx.x;
    const int w = t >> 5;
    const int l = t & 31;
    const int row  = w * 16 + (l >> 1);
    const int half = l & 1;
    const int m0   = 2 * half;          // this lane's first owned mode
    const int rowc = min(row, F - 1);
    const bool active = (row < F);
    const float* xb = x + b * XW;

    const int   steps  = *steps_p;
    const float length = *length_p;
    const float maxf   = *maxf_p;
    const float h  = length / (float)(steps - 1);
    const float h2 = 0.5f * h;
    const float h6 = h * (1.0f / 6.0f);

    if (t < 16) ovS[t] = overlap[t];
    for (int u = t; u < F; u += NT)
        frq[u] = (u < PNP) ? (C0F / xb[u]) : sig_freq[u - PNP];
    __syncthreads();

    // ---- this lane's 52 gains -> packed reg pairs ----
    ull gp[HALF / 2];
    {
        const float scale = (float)(Lr - 1) / maxf;
        const float fi = frq[rowc];
        #pragma unroll 4
        for (int k = 0; k < HALF / 2; ++k) {
            float gv[2];
            #pragma unroll
            for (int e = 0; e < 2; ++e) {
                const int j = half * HALF + 2 * k + e;
                const float fj = frq[j];
                const float fd = fj - fi;
                const float pos = fabsf(fd) * scale;
                int i0 = (int)floorf(pos);
                i0 = min(max(i0, 0), Lr - 2);
                const float wgt = pos - (float)i0;
                float g = raman[i0] * (1.0f - wgt) + raman[i0 + 1] * wgt;
                if (fd < 0.0f) g = -g;
                gv[e] = g * fmaxf(1.0f, fi / fj);
            }
            gp[k] = pk2(gv[0], gv[1]);
        }
    }

    // ---- per-lane RK state: ONLY this lane's two modes ----
    float lsA, lsB, pkA, pkB;
    if (rowc < PNP) {
        const float wn = xb[rowc] * 1e9f;
        const float lv = (lcoef[2] + lcoef[1] * wn + lcoef[0] * wn * wn) * ALPHA;
        lsA = lsB = lv;
        pkA = xb[PNP + 4 * rowc + m0];
        pkB = xb[PNP + 4 * rowc + m0 + 1];
    } else {
        const int u = 4 * rowc - PNP * MOD;
        lsA = sig_loss[u + m0]; lsB = sig_loss[u + m0 + 1];
        pkA = sig_pow[u + m0];  pkB = sig_pow[u + m0 + 1];
    }
    float pcA = pkA, pcB = pkB, acA = 0.f, acB = 0.f;

    // ---- prologue: Q(P0) into buffer 0 ----
    {
        const float u0 = __shfl_xor_sync(0xffffffffu, pkA, 1);
        const float u1 = __shfl_xor_sync(0xffffffffu, pkB, 1);
        const ull p01 = half ? pk2(u0, u1) : pk2(pkA, pkB);
        const ull p23 = half ? pk2(pkA, pkB) : pk2(u0, u1);
        const ulonglong2 ova = ((const ulonglong2*)ovS)[m0];
        const ulonglong2 ovb = ((const ulonglong2*)ovS)[m0 + 1];
        ull t0 = 0, t1 = 0;
        fma2(t0, ova.x, p01); fma2(t0, ova.y, p23);
        fma2(t1, ovb.x, p01); fma2(t1, ovb.y, p23);
        if (active) {
            Qt[(m0 + 0) * QSTR + row] = up2sum(t0);
            Qt[(m0 + 1) * QSTR + row] = up2sum(t1);
        }
    }
    __syncthreads();

    const int nst = 4 * (steps - 1);
    int cur = 0;
    float fo0 = 0.f, fo1 = 0.f, fo2 = 0.f, fo3 = 0.f;  // full P quad (for output)

    for (int it = 0; it < nst; ++it) {
        const int s4 = it & 3;
        // ---- matvec partials over this lane's 52 j's, all 4 modes ----
        ull a0 = 0, a1 = 0, a2 = 0, a3 = 0;
        const float* Qc = Qt + cur * QSZ + half * HALF;
        #pragma unroll
        for (int j4 = 0; j4 < HALF; j4 += 4) {
            const int k = j4 >> 1;
            const ulonglong2 q0 = *(const ulonglong2*)(Qc + 0 * QSTR + j4);
            const ulonglong2 q1 = *(const ulonglong2*)(Qc + 1 * QSTR + j4);
            const ulonglong2 q2 = *(const ulonglong2*)(Qc + 2 * QSTR + j4);
            const ulonglong2 q3 = *(const ulonglong2*)(Qc + 3 * QSTR + j4);
            fma2(a0, gp[k], q0.x); fma2(a0, gp[k + 1], q0.y);
            fma2(a1, gp[k], q1.x); fma2(a1, gp[k + 1], q1.y);
            fma2(a2, gp[k], q2.x); fma2(a2, gp[k + 1], q2.y);
            fma2(a3, gp[k], q3.x); fma2(a3, gp[k + 1], q3.y);
        }
        const float pA0 = up2sum(a0), pA1 = up2sum(a1);
        const float pA2 = up2sum(a2), pA3 = up2sum(a3);

        // exchange: lane needs partner's partials for ITS two modes only.
        // send what the partner needs (its modes), receive what I need.
        const float rA = __shfl_xor_sync(0xffffffffu, half ? pA0 : pA2, 1);
        const float rB = __shfl_xor_sync(0xffffffffu, half ? pA1 : pA3, 1);
        const float AmA = (half ? pA2 : pA0) + rA;
        const float AmB = (half ? pA3 : pA1) + rB;

        const float kA = (AmA - lsA) * pkA;
        const float kB = (AmB - lsB) * pkB;

        if (s4 == 0)      { acA = kA; acB = kB; }
        else if (s4 < 3)  { acA = fmaf(2.f, kA, acA); acB = fmaf(2.f, kB, acB); }
        else              { acA += kA; acB += kB; }

        if (s4 < 3) {
            const float cs = (s4 == 2) ? h : h2;
            pkA = fmaf(cs, kA, pcA);
            pkB = fmaf(cs, kB, pcB);
        } else {
            pkA = fmaf(h6, acA, pcA);
            pkB = fmaf(h6, acB, pcB);
            pcA = pkA; pcB = pkB;
        }

        // ---- rebuild full P quad, write this lane's 2 Q modes ----
        {
            const float u0 = __shfl_xor_sync(0xffffffffu, pkA, 1);
            const float u1 = __shfl_xor_sync(0xffffffffu, pkB, 1);
            fo0 = half ? u0 : pkA; fo1 = half ? u1 : pkB;
            fo2 = half ? pkA : u0; fo3 = half ? pkB : u1;
            const ull p01 = pk2(fo0, fo1), p23 = pk2(fo2, fo3);
            const ulonglong2 ova = ((const ulonglong2*)ovS)[m0];
            const ulonglong2 ovb = ((const ulonglong2*)ovS)[m0 + 1];
            ull t0 = 0, t1 = 0;
            fma2(t0, ova.x, p01); fma2(t0, ova.y, p23);
            fma2(t1, ovb.x, p01); fma2(t1, ovb.y, p23);
            float* Qn = Qt + (cur ^ 1) * QSZ;
            if (active) {
                Qn[(m0 + 0) * QSTR + row] = up2sum(t0);
                Qn[(m0 + 1) * QSTR + row] = up2sum(t1);
            }
        }
        __syncthreads();
        cur ^= 1;
    }

    if (active && row >= PNP && half == 0)
        *(float4*)(out + b * (NCH * MOD) + (row - PNP) * 4) =
            make_float4(fo0, fo1, fo2, fo3);
}

extern "C" void kernel_launch(void* const* d_in, const int* in_sizes, int n_in,
                              void* d_out, int out_size) {
    const float* x        = (const float*)d_in[0];
    const float* sig_freq = (const float*)d_in[1];
    const float* sig_pow  = (const float*)d_in[2];
    const float* sig_loss = (const float*)d_in[3];
    const float* lcoef    = (const float*)d_in[4];
    const float* overlap  = (const float*)d_in[5];
    const float* raman    = (const float*)d_in[6];
    const int*   steps_p  = (const int*)d_in[10];
    const float* length_p = (const float*)d_in[11];
    const float* maxf_p   = (const float*)d_in[12];

    const int B  = in_sizes[0] / XW;
    const int Lr = in_sizes[6];

    raman_kernel<<<B, NT>>>(x, sig_freq, sig_pow, sig_loss, lcoef, overlap,
                            raman, steps_p, length_p, maxf_p, Lr,
                            (float*)d_out);
}

// round 11
// speedup vs baseline: 1.1501x; 1.0839x over previous
#include <cuda_runtime.h>

namespace {
constexpr int PNP = 4;
constexpr int MOD = 4;
constexpr int NCH = 100;
constexpr int F   = NCH + PNP;       // 104
constexpr int XW  = PNP * (1 + MOD); // 20
constexpr int NT  = 224;             // 7 warps, 2 lanes/row
constexpr int HALF = 52;
constexpr int MSTR = 104;            // floats per mode (interleaved halves)
constexpr int QSZ  = MOD * MSTR;     // 416
constexpr float C0F   = 299792458.0f;
constexpr float ALPHA = 2.3025850929940457e-4f;
}

using ull = unsigned long long;

__device__ __forceinline__ ull pk2(float a, float b) {
    ull r; asm("mov.b64 %0,{%1,%2};" : "=l"(r) : "f"(a), "f"(b)); return r;
}
__device__ __forceinline__ void fma2(ull& d, ull a, ull b) {
    asm("fma.rn.f32x2 %0,%1,%2,%0;" : "+l"(d) : "l"(a), "l"(b));
}
__device__ __forceinline__ float up2sum(ull v) {
    float lo, hi; asm("mov.b64 {%0,%1},%2;" : "=f"(lo), "=f"(hi) : "l"(v));
    return lo + hi;
}

__global__ __launch_bounds__(NT, 4) void raman_kernel(
    const float* __restrict__ x,
    const float* __restrict__ sig_freq,
    const float* __restrict__ sig_pow,
    const float* __restrict__ sig_loss,
    const float* __restrict__ lcoef,
    const float* __restrict__ overlap,
    const float* __restrict__ raman,
    const int*   __restrict__ steps_p,
    const float* __restrict__ length_p,
    const float* __restrict__ maxf_p,
    int Lr,
    float* __restrict__ out)
{
    __shared__ __align__(16) float Qt[2 * QSZ];
    __shared__ __align__(16) float ovS[16];
    __shared__ float frq[F];

    const int b = blockIdx.x;
    const int t = threadIdx.x;
    const int w = t >> 5;
    const int l = t & 31;
    const int row  = w * 16 + (l >> 1);
    const int half = l & 1;
    const int m0   = 2 * half;          // this lane's first owned mode
    const int rowc = min(row, F - 1);
    const bool active = (row < F);
    const float* xb = x + b * XW;

    const int   steps  = *steps_p;
    const float length = *length_p;
    const float maxf   = *maxf_p;
    const float hstep = length / (float)(steps - 1);
    const float h2 = 0.5f * hstep;
    const float h6 = hstep * (1.0f / 6.0f);

    if (t < 16) ovS[t] = overlap[t];
    for (int u = t; u < F; u += NT)
        frq[u] = (u < PNP) ? (C0F / xb[u]) : sig_freq[u - PNP];
    __syncthreads();

    // ---- this lane's 52 gains -> packed reg pairs ----
    ull gp[HALF / 2];
    {
        const float scale = (float)(Lr - 1) / maxf;
        const float fi = frq[rowc];
        #pragma unroll 4
        for (int k = 0; k < HALF / 2; ++k) {
            float gv[2];
            #pragma unroll
            for (int e = 0; e < 2; ++e) {
                const int j = half * HALF + 2 * k + e;
                const float fj = frq[j];
                const float fd = fj - fi;
                const float pos = fabsf(fd) * scale;
                int i0 = (int)floorf(pos);
                i0 = min(max(i0, 0), Lr - 2);
                const float wgt = pos - (float)i0;
                float g = raman[i0] * (1.0f - wgt) + raman[i0 + 1] * wgt;
                if (fd < 0.0f) g = -g;
                gv[e] = g * fmaxf(1.0f, fi / fj);
            }
            gp[k] = pk2(gv[0], gv[1]);
        }
    }

    // ---- per-lane RK state: ONLY this lane's two modes ----
    float lsA, lsB, pkA, pkB;
    if (rowc < PNP) {
        const float wn = xb[rowc] * 1e9f;
        const float lv = (lcoef[2] + lcoef[1] * wn + lcoef[0] * wn * wn) * ALPHA;
        lsA = lsB = lv;
        pkA = xb[PNP + 4 * rowc + m0];
        pkB = xb[PNP + 4 * rowc + m0 + 1];
    } else {
        const int u = 4 * rowc - PNP * MOD;
        lsA = sig_loss[u + m0]; lsB = sig_loss[u + m0 + 1];
        pkA = sig_pow[u + m0];  pkB = sig_pow[u + m0 + 1];
    }
    float pcA = pkA, pcB = pkB, acA = 0.f, acB = 0.f;

    // interleaved write addresses for this row's two Q modes
    const int hf = (row >= HALF) ? 1 : 0;
    const int rr = row - hf * HALF;
    const int wA0 = m0 * MSTR + (rr >> 2) * 8 + hf * 4 + (rr & 3);
    const int wA1 = wA0 + MSTR;

    // ---- prologue: Q(P0) into buffer 0 ----
    {
        const float u0 = __shfl_xor_sync(0xffffffffu, pkA, 1);
        const float u1 = __shfl_xor_sync(0xffffffffu, pkB, 1);
        const ull p01 = half ? pk2(u0, u1) : pk2(pkA, pkB);
        const ull p23 = half ? pk2(pkA, pkB) : pk2(u0, u1);
        const ulonglong2 ova = ((const ulonglong2*)ovS)[m0];
        const ulonglong2 ovb = ((const ulonglong2*)ovS)[m0 + 1];
        ull t0 = 0, t1 = 0;
        fma2(t0, ova.x, p01); fma2(t0, ova.y, p23);
        fma2(t1, ovb.x, p01); fma2(t1, ovb.y, p23);
        if (active) { Qt[wA0] = up2sum(t0); Qt[wA1] = up2sum(t1); }
    }
    __syncthreads();

    float fo0 = 0.f, fo1 = 0.f, fo2 = 0.f, fo3 = 0.f;  // full P quad (output)

#define STAGE(S4, RD, WR)                                                     \
    {                                                                         \
        ull a0 = 0, a1 = 0, a2 = 0, a3 = 0;                                   \
        const float* Qc = Qt + (RD) * QSZ + half * 4;                         \
        _Pragma("unroll")                                                     \
        for (int q = 0; q < 13; ++q) {                                        \
            const float* bp = Qc + q * 8;                                     \
            const ulonglong2 q0 = *(const ulonglong2*)(bp + 0 * MSTR);        \
            const ulonglong2 q1 = *(const ulonglong2*)(bp + 1 * MSTR);        \
            const ulonglong2 q2 = *(const ulonglong2*)(bp + 2 * MSTR);        \
            const ulonglong2 q3 = *(const ulonglong2*)(bp + 3 * MSTR);        \
            fma2(a0, gp[2 * q], q0.x); fma2(a0, gp[2 * q + 1], q0.y);         \
            fma2(a1, gp[2 * q], q1.x); fma2(a1, gp[2 * q + 1], q1.y);         \
            fma2(a2, gp[2 * q], q2.x); fma2(a2, gp[2 * q + 1], q2.y);         \
            fma2(a3, gp[2 * q], q3.x); fma2(a3, gp[2 * q + 1], q3.y);         \
        }                                                                     \
        const float pA0 = up2sum(a0), pA1 = up2sum(a1);                       \
        const float pA2 = up2sum(a2), pA3 = up2sum(a3);                       \
        const float rA = __shfl_xor_sync(0xffffffffu, half ? pA0 : pA2, 1);   \
        const float rB = __shfl_xor_sync(0xffffffffu, half ? pA1 : pA3, 1);   \
        const float AmA = (half ? pA2 : pA0) + rA;                            \
        const float AmB = (half ? pA3 : pA1) + rB;                            \
        const float kA = (AmA - lsA) * pkA;                                   \
        const float kB = (AmB - lsB) * pkB;                                   \
        if ((S4) == 0)      { acA = kA; acB = kB; }                           \
        else if ((S4) < 3)  { acA = fmaf(2.f, kA, acA);                       \
                              acB = fmaf(2.f, kB, acB); }                     \
        else                { acA += kA; acB += kB; }                         \
        if ((S4) < 3) {                                                       \
            const float cs = ((S4) == 2) ? hstep : h2;                        \
            pkA = fmaf(cs, kA, pcA);                                          \
            pkB = fmaf(cs, kB, pcB);                                          \
        } else {                                                              \
            pkA = fmaf(h6, acA, pcA);                                         \
            pkB = fmaf(h6, acB, pcB);                                         \
            pcA = pkA; pcB = pkB;                                             \
        }                                                                     \
        {                                                                     \
            const float u0 = __shfl_xor_sync(0xffffffffu, pkA, 1);            \
            const float u1 = __shfl_xor_sync(0xffffffffu, pkB, 1);            \
            fo0 = half ? u0 : pkA; fo1 = half ? u1 : pkB;                     \
            fo2 = half ? pkA : u0; fo3 = half ? pkB : u1;                     \
            const ull p01 = pk2(fo0, fo1), p23 = pk2(fo2, fo3);               \
            const ulonglong2 ova = ((const ulonglong2*)ovS)[m0];              \
            const ulonglong2 ovb = ((const ulonglong2*)ovS)[m0 + 1];          \
            ull t0 = 0, t1 = 0;                                               \
            fma2(t0, ova.x, p01); fma2(t0, ova.y, p23);                       \
            fma2(t1, ovb.x, p01); fma2(t1, ovb.y, p23);                       \
            float* Qn = Qt + (WR) * QSZ;                                      \
            if (active) { Qn[wA0] = up2sum(t0); Qn[wA1] = up2sum(t1); }       \
        }                                                                     \
        __syncthreads();                                                      \
    }

    const int nsteps = steps - 1;
    for (int st = 0; st < nsteps; ++st) {
        STAGE(0, 0, 1)
        STAGE(1, 1, 0)
        STAGE(2, 0, 1)
        STAGE(3, 1, 0)
    }
#undef STAGE

    if (active && row >= PNP && half == 0)
        *(float4*)(out + b * (NCH * MOD) + (row - PNP) * 4) =
            make_float4(fo0, fo1, fo2, fo3);
}

extern "C" void kernel_launch(void* const* d_in, const int* in_sizes, int n_in,
                              void* d_out, int out_size) {
    const float* x        = (const float*)d_in[0];
    const float* sig_freq = (const float*)d_in[1];
    const float* sig_pow  = (const float*)d_in[2];
    const float* sig_loss = (const float*)d_in[3];
    const float* lcoef    = (const float*)d_in[4];
    const float* overlap  = (const float*)d_in[5];
    const float* raman    = (const float*)d_in[6];
    const int*   steps_p  = (const int*)d_in[10];
    const float* length_p = (const float*)d_in[11];
    const float* maxf_p   = (const float*)d_in[12];

    const int B  = in_sizes[0] / XW;
    const int Lr = in_sizes[6];

    raman_kernel<<<B, NT>>>(x, sig_freq, sig_pow, sig_loss, lcoef, overlap,
                            raman, steps_p, length_p, maxf_p, Lr,
                            (float*)d_out);
}